// round 5
// baseline (speedup 1.0000x reference)
#include <cuda_runtime.h>

#define L 256
#define BB 16
#define LL2 (L * L)
#define NEGF (-1000000000.0f)
#define NCHART BB
#define NBCE 32
#define NCTA (NCHART + NBCE)
#define TMAIN 1024
#define TRI ((L * (L + 1)) / 2)          // 32896 floats
#define SMEM_BYTES (TRI * 4)             // 131584 B

// -------- device scratch (no allocations allowed) --------
__device__ float  g_bS[BB * LL2];   // beta start-major: bS[i*L + w] = beta(i, i+w)
__device__ float  g_aS[BB * LL2];   // alpha start-major
__device__ float  g_aE[BB * LL2];   // alpha end-major: aE[j*L + w] = alpha(j-w, j)
__device__ float  g_lgT[BB * LL2];  // lgT[i*L + j] = lg[j*L + i]
__device__ int    g_lens[BB];
__device__ double g_span[BB];               // per-chart-CTA span log-sum (overwritten)
__device__ double g_bce1[NBCE], g_bce2[NBCE]; // per-BCE-CTA partials (overwritten)
__device__ unsigned long long g_ctr;        // monotone arrival counter (never reset)

__device__ __forceinline__ int roffE(int j) { return (j * (j + 1)) >> 1; }

__device__ __forceinline__ void lse_add(float& m, float& s, float v) {
    float nm = fmaxf(m, v);
    s = s * __expf(m - nm) + __expf(v - nm);
    m = nm;
}

__device__ __forceinline__ void warp_lse_merge(float m, float s, float& M, float& S) {
    #pragma unroll
    for (int o = 16; o; o >>= 1) {
        float om = __shfl_xor_sync(0xffffffffu, m, o);
        float os = __shfl_xor_sync(0xffffffffu, s, o);
        float nm = fmaxf(m, om);
        s = s * __expf(m - nm) + os * __expf(om - nm);
        m = nm;
    }
    M = m; S = s;
}

// dtype-robust length scan for batch b (all lanes of one warp; result in all lanes)
__device__ __forceinline__ int robust_len(const unsigned char* __restrict__ maskspan,
                                          int b, int lane) {
    const unsigned char* rowb = maskspan + (size_t)b * LL2;
    int c8 = 0;
    for (int j = lane; j < L; j += 32) c8 += (rowb[j] != 0) ? 1 : 0;
    #pragma unroll
    for (int o = 16; o; o >>= 1) c8 += __shfl_xor_sync(0xffffffffu, c8, o);
    int n;
    if (c8 >= 100 && rowb[0] == 1) {
        n = c8;
    } else {
        const unsigned int* rowi = ((const unsigned int*)maskspan) + (size_t)b * LL2;
        int c32 = 0;
        for (int j = lane; j < L; j += 32) c32 += (rowi[j] != 0u) ? 1 : 0;
        #pragma unroll
        for (int o = 16; o; o >>= 1) c32 += __shfl_xor_sync(0xffffffffu, c32, o);
        n = c32;
    }
    return max(1, min(L, n));
}

__global__ void __launch_bounds__(TMAIN, 1)
main_kernel(const float* __restrict__ lg_all,
            const float* __restrict__ ph_all,  const float* __restrict__ pt_all,
            const float* __restrict__ pharc_all,
            const int* __restrict__ spans_all,
            const int* __restrict__ phind_all, const int* __restrict__ ptind_all,
            const unsigned char* __restrict__ maskspan,
            float* __restrict__ out) {
    extern __shared__ float sE[];          // beta end-major triangular chart
    __shared__ double sh_red[32];
    __shared__ int    sh_n;
    __shared__ int    sh_lens[BB];

    const int cb   = blockIdx.x;
    const int tid  = threadIdx.x;
    const int lane = tid & 31;
    const int wid  = tid >> 5;

    if (cb < NCHART) {
        // ================= chart CTA: inside + outside + span loss for batch cb ======
        const int b = cb;
        if (wid == 0) {
            int n = robust_len(maskspan, b, lane);
            if (lane == 0) { sh_n = n; g_lens[b] = n; }
        }
        __syncthreads();
        const int n = sh_n;

        const float* __restrict__ lg    = lg_all    + (size_t)b * LL2;
        const float* __restrict__ pharc = pharc_all + (size_t)b * LL2;
        const int*   __restrict__ spans = spans_all + (size_t)b * LL2;
        float* __restrict__ bS  = g_bS  + (size_t)b * LL2;
        float* __restrict__ aS  = g_aS  + (size_t)b * LL2;
        float* __restrict__ aE  = g_aE  + (size_t)b * LL2;
        float* __restrict__ lgT = g_lgT + (size_t)b * LL2;

        // transpose lg: lgT[i][j] = lg[j][i]
        for (int idx = tid; idx < LL2; idx += TMAIN) {
            int i = idx >> 8, j = idx & (L - 1);
            lgT[idx] = __ldg(&lg[j * L + i]);
        }
        // width 0
        for (int i = tid; i < n; i += TMAIN) {
            float v = __ldg(&lg[i * L + i]);
            sE[roffE(i)] = v;       // beta(i,i) end-major
            bS[i * L]    = v;
        }
        __syncthreads();

        // ---- inside, widths 1..n-1 (warp per cell) ----
        for (int w = 1; w < n; ++w) {
            const int ncells = n - w;
            for (int i = wid; i < ncells; i += 32) {
                const float* __restrict__ Lr = bS + i * L;                 // [t] asc
                const float* __restrict__ Rr = sE + roffE(i + w) + (w - 1); // [-t] desc
                float m = NEGF, s = 0.f;
                for (int t = lane; t < w; t += 32)
                    lse_add(m, s, __ldg(Lr + t) + Rr[-t]);
                float M, S;
                warp_lse_merge(m, s, M, S);
                if (lane == 0) {
                    float res = M + __logf(S) + __ldg(&lg[i * L + i + w]);
                    sE[roffE(i + w) + w] = res;
                    bS[i * L + w]        = res;
                }
            }
            __syncthreads();
        }

        const float logZ = sE[roffE(n - 1) + (n - 1)];

        // ---- outside, widths n-1..0, loss fused (warp per cell) ----
        double acc = 0.0;
        for (int w = n - 1; w >= 0; --w) {
            const int ncells = n - w;
            for (int a = wid; a < ncells; a += 32) {
                const int bj = a + w;
                const int c1 = n - 1 - bj;
                const int T  = c1 + a;
                const float* __restrict__ A1 = aS  + a * L + (w + 1);      // [t]
                const float* __restrict__ G1 = lg  + a * L + (bj + 1);     // [t]
                const float* __restrict__ B1 = bS  + (bj + 1) * L;         // [t]
                const float* __restrict__ A2 = aE  + bj * L + bj;          // [-ii]
                const float* __restrict__ G2 = lgT + bj * L;               // [ii]
                const float* __restrict__ B2 = sE + roffE(a - 1) + (a - 1); // [-ii]
                float m = NEGF, s = 0.f;
                for (int t = lane; t < T; t += 32) {
                    float v;
                    if (t < c1) {
                        v = __ldg(A1 + t) + __ldg(G1 + t) + __ldg(B1 + t);
                    } else {
                        int ii = t - c1;
                        v = __ldg(A2 - ii) + __ldg(G2 + ii) + B2[-ii];
                    }
                    lse_add(m, s, v);
                }
                float M, S;
                warp_lse_merge(m, s, M, S);
                if (lane == 0) {
                    float alpha_v = (T > 0) ? (M + __logf(S)) : 0.f;       // root
                    aS[a * L + w]  = alpha_v;
                    aE[bj * L + w] = alpha_v;
                    float mu = __expf(alpha_v + sE[roffE(bj) + w] - logZ);
                    mu = fminf(mu, 1.0f);
                    float p  = 1.f / (1.f + __expf(-__ldg(&pharc[a * L + bj])));
                    float pm = p * mu;
                    acc += (__ldg(&spans[a * L + bj]) >= 2) ? (double)__logf(pm)
                                                            : (double)log1pf(-pm);
                }
            }
            __syncthreads();
        }

        // reduce span loss -> g_span[b] (overwrite)
        #pragma unroll
        for (int o = 16; o; o >>= 1) acc += __shfl_down_sync(0xffffffffu, acc, o);
        if (lane == 0) sh_red[wid] = acc;
        __syncthreads();
        if (wid == 0) {
            double v = sh_red[lane];
            #pragma unroll
            for (int o = 16; o; o >>= 1) v += __shfl_down_sync(0xffffffffu, v, o);
            if (lane == 0) g_span[b] = v;
        }
        __syncthreads();
    } else {
        // ================= BCE CTA: grid-stride over all batches =====================
        const int c = cb - NCHART;
        if (wid < BB) {
            int n = robust_len(maskspan, wid, lane);
            if (lane == 0) sh_lens[wid] = n;
        }
        __syncthreads();

        float f1 = 0.f, f2 = 0.f;
        const size_t total = (size_t)BB * LL2;
        for (size_t idx = (size_t)c * TMAIN + tid; idx < total; idx += (size_t)NBCE * TMAIN) {
            int bb = (int)(idx >> 16);
            int i  = (int)((idx >> 8) & (L - 1));
            int j  = (int)(idx & (L - 1));
            int nn = sh_lens[bb];
            if (i < nn && j < nn) {
                float x = __ldg(&ph_all[idx]);
                f1 += fmaxf(x, 0.f) + log1pf(__expf(-fabsf(x))) - x * (float)__ldg(&phind_all[idx]);
                float y = __ldg(&pt_all[idx]);
                f2 += fmaxf(y, 0.f) + log1pf(__expf(-fabsf(y))) - y * (float)__ldg(&ptind_all[idx]);
            }
        }
        #pragma unroll
        for (int o = 16; o; o >>= 1) {
            f1 += __shfl_down_sync(0xffffffffu, f1, o);
            f2 += __shfl_down_sync(0xffffffffu, f2, o);
        }
        if (lane == 0) sh_red[wid] = (double)f1;
        __syncthreads();
        if (wid == 0) {
            double v = sh_red[lane];
            #pragma unroll
            for (int o = 16; o; o >>= 1) v += __shfl_down_sync(0xffffffffu, v, o);
            if (lane == 0) g_bce1[c] = v;
        }
        __syncthreads();
        if (lane == 0) sh_red[wid] = (double)f2;
        __syncthreads();
        if (wid == 0) {
            double v = sh_red[lane];
            #pragma unroll
            for (int o = 16; o; o >>= 1) v += __shfl_down_sync(0xffffffffu, v, o);
            if (lane == 0) g_bce2[c] = v;
        }
        __syncthreads();
    }

    // ================= arrival protocol: last CTA computes the final scalar ==========
    if (tid == 0) {
        __threadfence();
        unsigned long long old = atomicAdd(&g_ctr, 1ULL);
        if ((old % (unsigned long long)NCTA) == (unsigned long long)(NCTA - 1)) {
            __threadfence();
            double span = 0.0, b1 = 0.0, b2 = 0.0, lsum = 0.0, sq = 0.0;
            for (int bb = 0; bb < BB; ++bb) {
                span += *((volatile double*)&g_span[bb]);
                double nn = (double)(*((volatile int*)&g_lens[bb]));
                lsum += nn; sq += nn * nn;
            }
            for (int k = 0; k < NBCE; ++k) {
                b1 += *((volatile double*)&g_bce1[k]);
                b2 += *((volatile double*)&g_bce2[k]);
            }
            double loss_spans = -span / lsum;
            double loss = 0.1 * loss_spans + 0.9 * (b1 / sq + b2 / sq);
            out[0] = (float)loss;
        }
    }
}

extern "C" void kernel_launch(void* const* d_in, const int* in_sizes, int n_in,
                              void* d_out, int out_size) {
    const float* span_logits = (const float*)d_in[0];
    const float* ph          = (const float*)d_in[1];
    const float* pt          = (const float*)d_in[2];
    const float* ph_arc      = (const float*)d_in[3];
    const int*   spans_ind   = (const int*)d_in[4];
    const int*   ph_ind      = (const int*)d_in[5];
    const int*   pt_ind      = (const int*)d_in[6];
    const unsigned char* maskspan = (const unsigned char*)d_in[8];

    (void)in_sizes; (void)n_in; (void)out_size;

    cudaFuncSetAttribute(main_kernel, cudaFuncAttributeMaxDynamicSharedMemorySize,
                         SMEM_BYTES);

    main_kernel<<<NCTA, TMAIN, SMEM_BYTES>>>(span_logits, ph, pt, ph_arc,
                                             spans_ind, ph_ind, pt_ind, maskspan,
                                             (float*)d_out);
}